// round 1
// baseline (speedup 1.0000x reference)
#include <cuda_runtime.h>
#include <math.h>

#define LAM 1.0
#define NTHREADS 256

// Hosking / Levinson-Durbin recursion. One CTA per batch.
// Produces exactly L @ (du * sqrt(D)) where L = chol(Toeplitz(r)) (innovations
// representation == unique Cholesky factor with positive diagonal), then fused
// cumsum + leading-zero output.
__global__ __launch_bounds__(NTHREADS, 1)
void fbm_hosking_kernel(const float* __restrict__ alpha,
                        const float* __restrict__ tau,
                        const float* __restrict__ diffusion,
                        const float* __restrict__ du,
                        float* __restrict__ out,
                        int T)
{
    const int N = T - 1;                 // 1023
    extern __shared__ double sh[];
    double* r   = sh;                    // [N]      autocovariance
    double* phi = r + N;                 // [N+1]    AR coefficients (index 1..)
    double* xh  = phi + (N + 1);         // [3*N]    generated increments per dim
    double* red = xh + 3 * (size_t)N;    // [32*7]   cross-warp reduction scratch
    double* bc  = red + 32 * 7;          // [8]      broadcast
    float*  zsh = (float*)(bc + 8);      // [N*3]    staged noise

    const int b     = blockIdx.x;
    const int tid   = threadIdx.x;
    const int lane  = tid & 31;
    const int warp  = tid >> 5;
    const int nwarp = blockDim.x >> 5;

    const double a  = (double)alpha[b];
    const double tb = (double)tau[b];
    const double sd = sqrt((double)diffusion[b]);

    // ---- autocovariance r[k] = 0.5((k+1)^a + |k-1|^a - 2 k^a), tapered ----
    for (int k = tid; k < N; k += blockDim.x) {
        double kp = pow((double)(k + 1), a);
        double km = (k == 1) ? 0.0 : pow((double)(k > 1 ? k - 1 : 1 - k), a);
        double k0 = (k == 0) ? 0.0 : pow((double)k, a);
        double R  = 0.5 * (kp + km - 2.0 * k0);
        double adt = (double)k;
        if (adt >= tb) R *= exp(-LAM * (adt - tb));
        r[k] = R;
    }
    // stage noise
    const float* dub = du + (size_t)b * N * 3;
    for (int i = tid; i < N * 3; i += blockDim.x) zsh[i] = dub[i];
    __syncthreads();

    // thread-0 persistent state
    double v = 0.0, cum0 = 0.0, cum1 = 0.0, cum2 = 0.0;
    if (tid == 0) {
        v = r[0];
        double sig = sqrt(v) * sd;
        double x0 = sig * (double)zsh[0];
        double x1 = sig * (double)zsh[1];
        double x2 = sig * (double)zsh[2];
        xh[0] = x0; xh[N] = x1; xh[2 * N] = x2;
        cum0 = x0; cum1 = x1; cum2 = x2;
        float* ob = out + (size_t)b * T * 3;
        ob[0] = 0.f; ob[1] = 0.f; ob[2] = 0.f;
        ob[3] = (float)cum0; ob[4] = (float)cum1; ob[5] = (float)cum2;
    }
    __syncthreads();

    for (int n = 1; n < N; n++) {
        // ---- Phase A: 7 fused partial dot products over k = 1..n-1 ----
        double p0 = 0, p1 = 0, p2 = 0, p3 = 0, p4 = 0, p5 = 0, p6 = 0;
        for (int k = tid + 1; k < n; k += blockDim.x) {
            double ph = phi[k];
            int m = n - k;
            p0 += ph * r[m];
            p1 += ph * xh[m];
            p2 += ph * xh[N + m];
            p3 += ph * xh[2 * N + m];
            p4 += ph * xh[k];
            p5 += ph * xh[N + k];
            p6 += ph * xh[2 * N + k];
        }
        #pragma unroll
        for (int o = 16; o > 0; o >>= 1) {
            p0 += __shfl_down_sync(0xffffffffu, p0, o);
            p1 += __shfl_down_sync(0xffffffffu, p1, o);
            p2 += __shfl_down_sync(0xffffffffu, p2, o);
            p3 += __shfl_down_sync(0xffffffffu, p3, o);
            p4 += __shfl_down_sync(0xffffffffu, p4, o);
            p5 += __shfl_down_sync(0xffffffffu, p5, o);
            p6 += __shfl_down_sync(0xffffffffu, p6, o);
        }
        if (lane == 0) {
            double* rw = red + warp * 7;
            rw[0] = p0; rw[1] = p1; rw[2] = p2; rw[3] = p3;
            rw[4] = p4; rw[5] = p5; rw[6] = p6;
        }
        __syncthreads();

        // ---- Phase B: scalar Durbin update + sample + cumsum (thread 0) ----
        if (tid == 0) {
            double s0 = 0, s1 = 0, s2 = 0, s3 = 0, s4 = 0, s5 = 0, s6 = 0;
            for (int w = 0; w < nwarp; w++) {
                const double* rw = red + w * 7;
                s0 += rw[0]; s1 += rw[1]; s2 += rw[2]; s3 += rw[3];
                s4 += rw[4]; s5 += rw[5]; s6 += rw[6];
            }
            double phinn = (r[n] - s0) / v;
            v *= (1.0 - phinn * phinn);
            double sig = sqrt(v) * sd;
            phi[n] = phinn;
            bc[0] = phinn;

            const float* zn = zsh + n * 3;
            double xn0 = s1 - phinn * s4 + phinn * xh[0]     + sig * (double)zn[0];
            double xn1 = s2 - phinn * s5 + phinn * xh[N]     + sig * (double)zn[1];
            double xn2 = s3 - phinn * s6 + phinn * xh[2 * N] + sig * (double)zn[2];
            xh[n] = xn0; xh[N + n] = xn1; xh[2 * N + n] = xn2;
            cum0 += xn0; cum1 += xn1; cum2 += xn2;
            float* o = out + ((size_t)b * T + n + 1) * 3;
            o[0] = (float)cum0; o[1] = (float)cum1; o[2] = (float)cum2;
        }
        __syncthreads();

        // ---- Phase C: in-place pairwise phi update ----
        double c = bc[0];
        int half = n >> 1;
        for (int k = tid + 1; k <= half; k += blockDim.x) {
            int m = n - k;
            double pa = phi[k];
            if (m == k) {
                phi[k] = pa - c * pa;
            } else {
                double pb = phi[m];
                phi[k] = pa - c * pb;
                phi[m] = pb - c * pa;
            }
        }
        __syncthreads();
    }
}

extern "C" void kernel_launch(void* const* d_in, const int* in_sizes, int n_in,
                              void* d_out, int out_size)
{
    const float* alpha = (const float*)d_in[0];
    const float* tau   = (const float*)d_in[1];
    const float* diffu = (const float*)d_in[2];
    const float* du    = (const float*)d_in[3];
    float* out = (float*)d_out;

    const int BS   = in_sizes[0];
    const int duN  = in_sizes[3] / BS;   // (T-1)*dim
    const int outN = out_size / BS;      // T*dim
    const int dim  = outN - duN;         // = 3
    const int T    = outN / dim;
    const int N    = T - 1;

    size_t smem = (size_t)(N + (N + 1) + 3 * N + 32 * 7 + 8) * sizeof(double)
                + (size_t)N * 3 * sizeof(float);

    cudaFuncSetAttribute(fbm_hosking_kernel,
                         cudaFuncAttributeMaxDynamicSharedMemorySize, (int)smem);

    fbm_hosking_kernel<<<BS, NTHREADS, smem>>>(alpha, tau, diffu, du, out, T);
}

// round 2
// speedup vs baseline: 9.4990x; 9.4990x over previous
#include <cuda_runtime.h>
#include <math.h>

#define LAM 1.0
#define NT 256

// Hosking / Levinson-Durbin recursion, all-fp32 data path.
// One CTA per batch. Covariance built in fp64 (real cancellation), recursion,
// dots, and sampling in fp32. 2 barriers per step; no serialized thread-0
// fp64 chains; cumsum + output deferred past the loop.
__global__ __launch_bounds__(NT, 1)
void fbm_hosking_f32(const float* __restrict__ alpha,
                     const float* __restrict__ tau,
                     const float* __restrict__ diffusion,
                     const float* __restrict__ du,
                     float* __restrict__ out,
                     int T)
{
    const int N = T - 1;                  // 1023
    extern __shared__ float sh[];
    float* r   = sh;                      // [N]    autocovariance (fp32)
    float* phi = r + N;                   // [N+1]  AR coefficients
    float* xh  = phi + (N + 1);           // [3*N]  increments per dim
    float* red = xh + 3 * N;              // [8*8]  per-warp partials (7 used)
    float* zsh = red + 64;                // [3*N]  staged noise

    const int b    = blockIdx.x;
    const int tid  = threadIdx.x;
    const int lane = tid & 31;
    const int warp = tid >> 5;

    const double a  = (double)alpha[b];
    const float  tb = tau[b];
    const float  sd = sqrtf(diffusion[b]);

    // ---- fp64 one-time covariance: r[k] = 0.5((k+1)^a + |k-1|^a - 2 k^a), tapered
    for (int k = tid; k < N; k += NT) {
        double kp = pow((double)(k + 1), a);
        double km = (k == 1) ? 0.0 : pow((double)(k >= 1 ? k - 1 : 1 - k), a);
        double k0 = (k == 0) ? 0.0 : pow((double)k, a);
        double R  = 0.5 * (kp + km - 2.0 * k0);
        if ((float)k >= tb) R *= exp(-LAM * (double)((float)k - tb));
        r[k] = (float)R;
    }
    const float* dub = du + (size_t)b * N * 3;
    for (int i = tid; i < N * 3; i += NT) zsh[i] = dub[i];
    __syncthreads();

    // replicated scalar state: identical ops on identical inputs -> bitwise equal
    float v = r[0];
    if (tid < 3) xh[tid * N] = sqrtf(v) * sd * zsh[tid];   // x_0 per dim
    __syncthreads();

    const float* x0 = xh;
    const float* x1 = xh + N;
    const float* x2 = xh + 2 * N;

    for (int n = 1; n < N; n++) {
        // ---- Phase A: 7 fused fp32 partial dots over k = 1..n-1 ----
        float p0 = 0.f, p1 = 0.f, p2 = 0.f, p3 = 0.f, p4 = 0.f, p5 = 0.f, p6 = 0.f;
        for (int k = tid + 1; k < n; k += NT) {
            float ph = phi[k];
            int m = n - k;
            p0 += ph * r[m];
            p1 += ph * x0[m];
            p2 += ph * x1[m];
            p3 += ph * x2[m];
            p4 += ph * x0[k];
            p5 += ph * x1[k];
            p6 += ph * x2[k];
        }
        #pragma unroll
        for (int o = 16; o > 0; o >>= 1) {
            p0 += __shfl_down_sync(0xffffffffu, p0, o);
            p1 += __shfl_down_sync(0xffffffffu, p1, o);
            p2 += __shfl_down_sync(0xffffffffu, p2, o);
            p3 += __shfl_down_sync(0xffffffffu, p3, o);
            p4 += __shfl_down_sync(0xffffffffu, p4, o);
            p5 += __shfl_down_sync(0xffffffffu, p5, o);
            p6 += __shfl_down_sync(0xffffffffu, p6, o);
        }
        if (lane == 0) {
            float* rw = red + warp * 8;
            rw[0] = p0; rw[1] = p1; rw[2] = p2; rw[3] = p3;
            rw[4] = p4; rw[5] = p5; rw[6] = p6;
        }
        __syncthreads();   // bar1: partials visible, phi/xh reads complete

        // ---- Phase B: replicated Durbin update (all threads, broadcast LDS) ----
        float s0 = ((red[0]      + red[8])      + (red[16]     + red[24]))
                 + ((red[32]     + red[40])     + (red[48]     + red[56]));
        float phinn = (r[n] - s0) / v;
        v *= (1.f - phinn * phinn);

        // threads 0..2: sample x_n for their dim (fully parallel, no shuffles)
        if (tid < 3) {
            int j = 1 + tid;
            float sA = ((red[j]      + red[8 + j])  + (red[16 + j] + red[24 + j]))
                     + ((red[32 + j] + red[40 + j]) + (red[48 + j] + red[56 + j]));
            int q = 4 + tid;
            float sB = ((red[q]      + red[8 + q])  + (red[16 + q] + red[24 + q]))
                     + ((red[32 + q] + red[40 + q]) + (red[48 + q] + red[56 + q]));
            float xn = sA - phinn * sB + phinn * xh[tid * N]
                     + sqrtf(v) * sd * zsh[n * 3 + tid];
            xh[tid * N + n] = xn;
        }
        if (tid == 0) phi[n] = phinn;

        // ---- Phase C: in-place pairwise phi update (local phinn, no broadcast) ----
        int half = n >> 1;
        for (int k = tid + 1; k <= half; k += NT) {
            int m = n - k;
            float pa = phi[k];
            if (m == k) {
                phi[k] = pa - phinn * pa;
            } else {
                float pb = phi[m];
                phi[k] = pa - phinn * pb;
                phi[m] = pb - phinn * pa;
            }
        }
        __syncthreads();   // bar2: phi + xh[n] visible for next iteration
    }

    // ---- post-loop: cumsum per dim, then coalesced output ----
    if (tid < 3) {
        float* xp = xh + tid * N;
        float c = 0.f;
        for (int i = 0; i < N; i++) { c += xp[i]; xp[i] = c; }
    }
    __syncthreads();

    float* ob = out + (size_t)b * T * 3;
    for (int i = tid; i < T * 3; i += NT) {
        int t = i / 3, d = i - 3 * t;
        ob[i] = (t == 0) ? 0.f : xh[d * N + (t - 1)];
    }
}

extern "C" void kernel_launch(void* const* d_in, const int* in_sizes, int n_in,
                              void* d_out, int out_size)
{
    const float* alpha = (const float*)d_in[0];
    const float* tau   = (const float*)d_in[1];
    const float* diffu = (const float*)d_in[2];
    const float* du    = (const float*)d_in[3];
    float* out = (float*)d_out;

    const int BS   = in_sizes[0];
    const int duN  = in_sizes[3] / BS;   // (T-1)*dim
    const int outN = out_size / BS;      // T*dim
    const int dim  = outN - duN;         // 3
    const int T    = outN / dim;
    const int N    = T - 1;

    size_t smem = (size_t)(N + (N + 1) + 3 * N + 64 + 3 * N) * sizeof(float);

    cudaFuncSetAttribute(fbm_hosking_f32,
                         cudaFuncAttributeMaxDynamicSharedMemorySize, (int)smem);

    fbm_hosking_f32<<<BS, NT, smem>>>(alpha, tau, diffu, du, out, T);
}